// round 1
// baseline (speedup 1.0000x reference)
#include <cuda_runtime.h>
#include <cstdint>
#include <math.h>

// Problem constants
#define T_    64
#define B_    256
#define FEAT_ 924
#define H_    512
#define NC_   151
#define ED_   100
#define KIN_  (FEAT_ + ED_)   // 1024
#define SIXH_ (6 * H_)        // 3072

// ---------------------------------------------------------------------------
// Scratch (static device globals — no runtime allocation allowed)
// ---------------------------------------------------------------------------
__device__ float g_TI[(size_t)T_ * B_ * KIN_];   // concat(x, emb)   64 MB
__device__ float g_PI[(size_t)T_ * B_ * SIXH_];  // input gemm out  192 MB
__device__ float g_H [(size_t)T_ * B_ * H_];     // all hidden states 32 MB
__device__ float g_h0[B_ * H_];                  // zero h0
__device__ float g_c [B_ * H_];                  // cell state (in-place)

// ---------------------------------------------------------------------------
// Init: zero h0 and c
// ---------------------------------------------------------------------------
__global__ void k_init() {
    int i = blockIdx.x * blockDim.x + threadIdx.x;
    if (i < B_ * H_) { g_h0[i] = 0.f; g_c[i] = 0.f; }
}

// ---------------------------------------------------------------------------
// Concat: TI[row][k] = k<FEAT ? x[row][k] : embed[labels[row]][k-FEAT]
// FEAT=924 and ED=100 are both multiples of 4 -> safe float4 path
// ---------------------------------------------------------------------------
__global__ void k_concat(const float* __restrict__ x,
                         const int*   __restrict__ labels,
                         const float* __restrict__ embed) {
    const int C4 = KIN_ / 4;                 // 256
    int idx = blockIdx.x * blockDim.x + threadIdx.x;
    if (idx >= T_ * B_ * C4) return;
    int row = idx / C4;
    int c   = (idx % C4) * 4;
    float4 v;
    if (c < FEAT_) {
        v = *reinterpret_cast<const float4*>(x + (size_t)row * FEAT_ + c);
    } else {
        int lab = labels[row];
        v = *reinterpret_cast<const float4*>(embed + (size_t)lab * ED_ + (c - FEAT_));
    }
    *reinterpret_cast<float4*>(g_TI + (size_t)row * KIN_ + c) = v;
}

// ---------------------------------------------------------------------------
// Generic SGEMM: C[M,N] = A[M,K] @ B[N,K]^T + bias[N]
// (both A and B row-major with K contiguous)
// 128x128 tile, BK=8, 256 threads, 8x8 per-thread microtile.
// Requires M % 128 == 0 and K % 8 == 0 (true for all uses here); N guarded.
// ---------------------------------------------------------------------------
__global__ __launch_bounds__(256)
void k_sgemm(int M, int N, int K,
             const float* __restrict__ A,
             const float* __restrict__ B,
             const float* __restrict__ bias,
             float* __restrict__ C) {
    constexpr int BM = 128, BN = 128, BK = 8, TM = 8, TN = 8;
    __shared__ float As[BK][BM];
    __shared__ float Bs[BK][BN];

    const int tid = threadIdx.x;
    const int m0  = blockIdx.y * BM;
    const int n0  = blockIdx.x * BN;

    const int trow = tid / (BN / TN);        // 0..15
    const int tcol = tid % (BN / TN);        // 0..15

    // loader mapping: 2 float4 slots per row of 8 -> tid/2 picks row, tid%2 picks half
    const int a_row = tid >> 1;              // 0..127
    const int a_col = (tid & 1) * 4;         // 0 or 4

    float acc[TM][TN];
#pragma unroll
    for (int i = 0; i < TM; i++)
#pragma unroll
        for (int j = 0; j < TN; j++) acc[i][j] = 0.f;

    for (int k0 = 0; k0 < K; k0 += BK) {
        // load A tile (128 x 8)
        {
            int gm = m0 + a_row;
            float4 v = make_float4(0.f, 0.f, 0.f, 0.f);
            if (gm < M) v = *reinterpret_cast<const float4*>(A + (size_t)gm * K + k0 + a_col);
            As[a_col + 0][a_row] = v.x;
            As[a_col + 1][a_row] = v.y;
            As[a_col + 2][a_row] = v.z;
            As[a_col + 3][a_row] = v.w;
        }
        // load B tile (128 x 8)
        {
            int gn = n0 + a_row;
            float4 v = make_float4(0.f, 0.f, 0.f, 0.f);
            if (gn < N) v = *reinterpret_cast<const float4*>(B + (size_t)gn * K + k0 + a_col);
            Bs[a_col + 0][a_row] = v.x;
            Bs[a_col + 1][a_row] = v.y;
            Bs[a_col + 2][a_row] = v.z;
            Bs[a_col + 3][a_row] = v.w;
        }
        __syncthreads();

#pragma unroll
        for (int kk = 0; kk < BK; kk++) {
            float a[TM], b[TN];
            *reinterpret_cast<float4*>(&a[0]) = *reinterpret_cast<const float4*>(&As[kk][trow * TM + 0]);
            *reinterpret_cast<float4*>(&a[4]) = *reinterpret_cast<const float4*>(&As[kk][trow * TM + 4]);
            *reinterpret_cast<float4*>(&b[0]) = *reinterpret_cast<const float4*>(&Bs[kk][tcol * TN + 0]);
            *reinterpret_cast<float4*>(&b[4]) = *reinterpret_cast<const float4*>(&Bs[kk][tcol * TN + 4]);
#pragma unroll
            for (int i = 0; i < TM; i++)
#pragma unroll
                for (int j = 0; j < TN; j++)
                    acc[i][j] = fmaf(a[i], b[j], acc[i][j]);
        }
        __syncthreads();
    }

#pragma unroll
    for (int i = 0; i < TM; i++) {
        int gm = m0 + trow * TM + i;
        if (gm >= M) continue;
#pragma unroll
        for (int j = 0; j < TN; j++) {
            int gn = n0 + tcol * TN + j;
            if (gn < N) C[(size_t)gm * N + gn] = acc[i][j] + bias[gn];
        }
    }
}

// ---------------------------------------------------------------------------
// Fused recurrent step:
//   ps[b, g*H+n] = h_prev[b,:] @ Ws[g*H+n,:]^T + bs  for g = 0..4
//   gates + cell update + highway + dropout in the epilogue.
// Each CTA computes a 32(b) x 32(n) tile for ALL 5 gates so the epilogue
// has every ps value it needs locally.  Grid = (H/32, B/32) = (16, 8).
// ---------------------------------------------------------------------------
__device__ __forceinline__ float sigmoidf_(float x) {
    return 1.f / (1.f + expf(-x));
}

__global__ __launch_bounds__(256)
void k_step(int t,
            const float* __restrict__ Ws,    // (5H, H)
            const float* __restrict__ bs,    // (5H)
            const float* __restrict__ mask)  // (B, H)
{
    constexpr int BM = 32, BN = 32, BK = 16;
    __shared__ float Hs[BK][BM];             // [k][b]
    __shared__ float Wss[5][BK][BN];         // [g][k][n]

    const int tid = threadIdx.x;
    const int n0  = blockIdx.x * BN;
    const int m0  = blockIdx.y * BM;

    const float* __restrict__ hprev = (t == 0) ? g_h0 : (g_H + (size_t)(t - 1) * B_ * H_);
    const float* __restrict__ pi_t  = g_PI + (size_t)t * B_ * SIXH_;
    float*       __restrict__ hout  = g_H + (size_t)t * B_ * H_;

    const int trow = tid / 16;               // 0..15 -> 2 b-rows
    const int tcol = tid % 16;               // 0..15 -> 2 n-cols

    float acc[5][2][2];
#pragma unroll
    for (int g = 0; g < 5; g++)
#pragma unroll
        for (int i = 0; i < 2; i++)
#pragma unroll
            for (int j = 0; j < 2; j++) acc[g][i][j] = 0.f;

    for (int k0 = 0; k0 < H_; k0 += BK) {
        // load h tile: 32 rows x 16 cols = 128 float4
        if (tid < 128) {
            int r = tid >> 2;                // 0..31
            int c = (tid & 3) * 4;           // 0,4,8,12
            float4 v = *reinterpret_cast<const float4*>(hprev + (size_t)(m0 + r) * H_ + k0 + c);
            Hs[c + 0][r] = v.x; Hs[c + 1][r] = v.y;
            Hs[c + 2][r] = v.z; Hs[c + 3][r] = v.w;
        }
        // load 5 Ws tiles: 5*32 rows x 16 cols = 640 float4
#pragma unroll
        for (int i = tid; i < 5 * BN * (BK / 4); i += 256) {
            int g   = i / (BN * (BK / 4));
            int rem = i % (BN * (BK / 4));
            int r   = rem / (BK / 4);
            int c   = (rem % (BK / 4)) * 4;
            float4 v = *reinterpret_cast<const float4*>(Ws + (size_t)(g * H_ + n0 + r) * H_ + k0 + c);
            Wss[g][c + 0][r] = v.x; Wss[g][c + 1][r] = v.y;
            Wss[g][c + 2][r] = v.z; Wss[g][c + 3][r] = v.w;
        }
        __syncthreads();

#pragma unroll
        for (int kk = 0; kk < BK; kk++) {
            float a0 = Hs[kk][trow * 2 + 0];
            float a1 = Hs[kk][trow * 2 + 1];
#pragma unroll
            for (int g = 0; g < 5; g++) {
                float b0 = Wss[g][kk][tcol * 2 + 0];
                float b1 = Wss[g][kk][tcol * 2 + 1];
                acc[g][0][0] = fmaf(a0, b0, acc[g][0][0]);
                acc[g][0][1] = fmaf(a0, b1, acc[g][0][1]);
                acc[g][1][0] = fmaf(a1, b0, acc[g][1][0]);
                acc[g][1][1] = fmaf(a1, b1, acc[g][1][1]);
            }
        }
        __syncthreads();
    }

    // epilogue: gates + cell + highway + dropout
#pragma unroll
    for (int i = 0; i < 2; i++) {
        int b = m0 + trow * 2 + i;
        const float* pi = pi_t + (size_t)b * SIXH_;
#pragma unroll
        for (int j = 0; j < 2; j++) {
            int n = n0 + tcol * 2 + j;
            float ps0 = acc[0][i][j] + bs[0 * H_ + n];
            float ps1 = acc[1][i][j] + bs[1 * H_ + n];
            float ps2 = acc[2][i][j] + bs[2 * H_ + n];
            float ps3 = acc[3][i][j] + bs[3 * H_ + n];
            float ps4 = acc[4][i][j] + bs[4 * H_ + n];

            float ig = sigmoidf_(pi[0 * H_ + n] + ps0);
            float fg = sigmoidf_(pi[1 * H_ + n] + ps1);
            float mi = tanhf   (pi[2 * H_ + n] + ps2);
            float og = sigmoidf_(pi[3 * H_ + n] + ps3);
            float hg = sigmoidf_(pi[4 * H_ + n] + ps4);

            float c_old = g_c[b * H_ + n];
            float c_new = ig * mi + fg * c_old;
            float out   = og * tanhf(c_new);
            out = hg * out + (1.f - hg) * pi[5 * H_ + n];
            out *= mask[b * H_ + n];

            g_c[b * H_ + n] = c_new;
            hout[(size_t)b * H_ + n] = out;
        }
    }
}

// ---------------------------------------------------------------------------
// kernel_launch
// Input order (metadata): x, labels, embed, Wi, bi, Ws, bs, Wo, bo, mask
// ---------------------------------------------------------------------------
extern "C" void kernel_launch(void* const* d_in, const int* in_sizes, int n_in,
                              void* d_out, int out_size) {
    const float* x      = (const float*)d_in[0];
    const int*   labels = (const int*)  d_in[1];
    const float* embed  = (const float*)d_in[2];
    const float* Wi     = (const float*)d_in[3];
    const float* bi     = (const float*)d_in[4];
    const float* Ws     = (const float*)d_in[5];
    const float* bs     = (const float*)d_in[6];
    const float* Wo     = (const float*)d_in[7];
    const float* bo     = (const float*)d_in[8];
    const float* mask   = (const float*)d_in[9];
    float* out = (float*)d_out;

    float *ti, *pi, *hall;
    cudaGetSymbolAddress((void**)&ti,   g_TI);
    cudaGetSymbolAddress((void**)&pi,   g_PI);
    cudaGetSymbolAddress((void**)&hall, g_H);

    // 1) init h0 / c
    k_init<<<(B_ * H_ + 255) / 256, 256>>>();

    // 2) concat(x, embed[labels]) -> TI
    {
        int total = T_ * B_ * (KIN_ / 4);
        k_concat<<<(total + 255) / 256, 256>>>(x, labels, embed);
    }

    // 3) PI = TI @ Wi^T + bi   (16384 x 3072 x 1024)
    {
        dim3 grid(SIXH_ / 128, (T_ * B_) / 128);
        k_sgemm<<<grid, 256>>>(T_ * B_, SIXH_, KIN_, ti, Wi, bi, pi);
    }

    // 4) recurrence: 64 fused steps
    {
        dim3 grid(H_ / 32, B_ / 32);   // (16, 8)
        for (int t = 0; t < T_; t++) {
            k_step<<<grid, 256>>>(t, Ws, bs, mask);
        }
    }

    // 5) OUT = H_all @ Wo^T + bo   (16384 x 151 x 512)
    {
        dim3 grid((NC_ + 127) / 128, (T_ * B_) / 128);
        k_sgemm<<<grid, 256>>>(T_ * B_, NC_, H_, hall, Wo, bo, out);
    }
}

// round 2
// speedup vs baseline: 1.2192x; 1.2192x over previous
#include <cuda_runtime.h>
#include <cstdint>
#include <math.h>

// Problem constants
#define T_    64
#define B_    256
#define FEAT_ 924
#define H_    512
#define NC_   151
#define ED_   100
#define KIN_  (FEAT_ + ED_)   // 1024
#define SIXH_ (6 * H_)        // 3072

#define NCTA_  128            // persistent grid: 32 n-tiles x 4 b-tiles
#define NTILE_ 16             // columns per CTA
#define BTILE_ 64             // batch rows per CTA

// ---------------------------------------------------------------------------
// Scratch (static device globals — no runtime allocation allowed)
// ---------------------------------------------------------------------------
__device__ float g_TI[(size_t)T_ * B_ * KIN_];   // concat(x, emb)
__device__ float g_PI[(size_t)T_ * B_ * SIXH_];  // input gemm out
__device__ float g_H [(size_t)T_ * B_ * H_];     // all hidden states

// grid-barrier state (g_arrive returns to 0 after every barrier; g_gen is
// monotonically increasing — each launch captures its base value first)
__device__ unsigned g_arrive = 0;
__device__ unsigned g_gen    = 0;

// ---------------------------------------------------------------------------
// Concat: TI[row][k] = k<FEAT ? x[row][k] : embed[labels[row]][k-FEAT]
// ---------------------------------------------------------------------------
__global__ void k_concat(const float* __restrict__ x,
                         const int*   __restrict__ labels,
                         const float* __restrict__ embed) {
    const int C4 = KIN_ / 4;
    int idx = blockIdx.x * blockDim.x + threadIdx.x;
    if (idx >= T_ * B_ * C4) return;
    int row = idx / C4;
    int c   = (idx % C4) * 4;
    float4 v;
    if (c < FEAT_) {
        v = *reinterpret_cast<const float4*>(x + (size_t)row * FEAT_ + c);
    } else {
        int lab = labels[row];
        v = *reinterpret_cast<const float4*>(embed + (size_t)lab * ED_ + (c - FEAT_));
    }
    *reinterpret_cast<float4*>(g_TI + (size_t)row * KIN_ + c) = v;
}

// ---------------------------------------------------------------------------
// Generic SGEMM: C[M,N] = A[M,K] @ B[N,K]^T + bias[N]
// 128x128 tile, BK=8, 256 threads, 8x8 microtile. (unchanged from R1)
// ---------------------------------------------------------------------------
__global__ __launch_bounds__(256)
void k_sgemm(int M, int N, int K,
             const float* __restrict__ A,
             const float* __restrict__ B,
             const float* __restrict__ bias,
             float* __restrict__ C) {
    constexpr int BM = 128, BN = 128, BK = 8, TM = 8, TN = 8;
    __shared__ float As[BK][BM];
    __shared__ float Bs[BK][BN];

    const int tid = threadIdx.x;
    const int m0  = blockIdx.y * BM;
    const int n0  = blockIdx.x * BN;
    const int trow = tid / (BN / TN);
    const int tcol = tid % (BN / TN);
    const int a_row = tid >> 1;
    const int a_col = (tid & 1) * 4;

    float acc[TM][TN];
#pragma unroll
    for (int i = 0; i < TM; i++)
#pragma unroll
        for (int j = 0; j < TN; j++) acc[i][j] = 0.f;

    for (int k0 = 0; k0 < K; k0 += BK) {
        {
            int gm = m0 + a_row;
            float4 v = make_float4(0.f, 0.f, 0.f, 0.f);
            if (gm < M) v = *reinterpret_cast<const float4*>(A + (size_t)gm * K + k0 + a_col);
            As[a_col + 0][a_row] = v.x;
            As[a_col + 1][a_row] = v.y;
            As[a_col + 2][a_row] = v.z;
            As[a_col + 3][a_row] = v.w;
        }
        {
            int gn = n0 + a_row;
            float4 v = make_float4(0.f, 0.f, 0.f, 0.f);
            if (gn < N) v = *reinterpret_cast<const float4*>(B + (size_t)gn * K + k0 + a_col);
            Bs[a_col + 0][a_row] = v.x;
            Bs[a_col + 1][a_row] = v.y;
            Bs[a_col + 2][a_row] = v.z;
            Bs[a_col + 3][a_row] = v.w;
        }
        __syncthreads();

#pragma unroll
        for (int kk = 0; kk < BK; kk++) {
            float a[TM], b[TN];
            *reinterpret_cast<float4*>(&a[0]) = *reinterpret_cast<const float4*>(&As[kk][trow * TM + 0]);
            *reinterpret_cast<float4*>(&a[4]) = *reinterpret_cast<const float4*>(&As[kk][trow * TM + 4]);
            *reinterpret_cast<float4*>(&b[0]) = *reinterpret_cast<const float4*>(&Bs[kk][tcol * TN + 0]);
            *reinterpret_cast<float4*>(&b[4]) = *reinterpret_cast<const float4*>(&Bs[kk][tcol * TN + 4]);
#pragma unroll
            for (int i = 0; i < TM; i++)
#pragma unroll
                for (int j = 0; j < TN; j++)
                    acc[i][j] = fmaf(a[i], b[j], acc[i][j]);
        }
        __syncthreads();
    }

#pragma unroll
    for (int i = 0; i < TM; i++) {
        int gm = m0 + trow * TM + i;
        if (gm >= M) continue;
#pragma unroll
        for (int j = 0; j < TN; j++) {
            int gn = n0 + tcol * TN + j;
            if (gn < N) C[(size_t)gm * N + gn] = acc[i][j] + bias[gn];
        }
    }
}

// ---------------------------------------------------------------------------
// Persistent recurrence kernel.
//   grid = 128 CTAs = 32 n-tiles (16 cols) x 4 b-tiles (64 rows), 256 threads.
//   Ws slice (5 gates x 16 cols x 512 k = 160 KB) resident in smem all steps.
//   Per-thread: 4 rows x 1 col x 5 gates accumulators; c & mask in registers.
//   Grid barrier (atomic arrive + acquire spin on generation) between steps.
// ---------------------------------------------------------------------------
__device__ __forceinline__ float sigmoidf_(float x) {
    return 1.f / (1.f + __expf(-x));
}

#define W_COLS 80                    // 5 gates * 16 cols
#define AS_W   68                    // 64 rows + pad (stride 272B = 17*16, float4-aligned)
#define AS_ELE (32 * AS_W)           // one K-chunk buffer

__global__ __launch_bounds__(256, 1)
void k_recur(const float* __restrict__ Ws,    // (5H, H)
             const float* __restrict__ bs,    // (5H)
             const float* __restrict__ mask)  // (B, H)
{
    extern __shared__ float smem[];
    float* Wsm = smem;                        // [512][80]
    float* As  = smem + 512 * W_COLS;         // [2][32][AS_W]

    const int tid  = threadIdx.x;
    const int nt   = blockIdx.x & 31;         // n-tile
    const int bt   = blockIdx.x >> 5;         // b-tile
    const int n0   = nt * NTILE_;
    const int b0   = bt * BTILE_;

    const int trow = tid >> 4;                // 0..15 -> 4 rows each
    const int tcol = tid & 15;                // 0..15 -> 1 col
    const int n    = n0 + tcol;

    // capture barrier generation base (before any CTA can arrive anywhere)
    __shared__ unsigned s_base;
    if (tid == 0) {
        unsigned v;
        asm volatile("ld.acquire.gpu.global.u32 %0, [%1];" : "=r"(v) : "l"(&g_gen));
        s_base = v;
    }

    // ---- preload Ws slice into smem:  Wsm[k][g*16+j] = Ws[g*H+n0+j][k]
    for (int s = tid; s < W_COLS * (H_ / 4); s += 256) {
        int k4 = s / W_COLS;                  // 0..127
        int vr = s % W_COLS;                  // g*16+j
        int g  = vr >> 4, j = vr & 15;
        float4 v = *reinterpret_cast<const float4*>(
            Ws + (size_t)(g * H_ + n0 + j) * H_ + k4 * 4);
        Wsm[(k4 * 4 + 0) * W_COLS + vr] = v.x;
        Wsm[(k4 * 4 + 1) * W_COLS + vr] = v.y;
        Wsm[(k4 * 4 + 2) * W_COLS + vr] = v.z;
        Wsm[(k4 * 4 + 3) * W_COLS + vr] = v.w;
    }

    // per-thread persistent state
    float c_reg[4] = {0.f, 0.f, 0.f, 0.f};
    float m_reg[4], bsr[5];
#pragma unroll
    for (int i = 0; i < 4; i++) m_reg[i] = mask[(size_t)(b0 + trow * 4 + i) * H_ + n];
#pragma unroll
    for (int g = 0; g < 5; g++) bsr[g] = bs[g * H_ + n];

    __syncthreads();
    const unsigned base = s_base;

    // h-panel loader slot mapping: thread covers slots tid and tid+256
    const int lr = tid >> 3;                  // row 0..31 (second slot: +32)
    const int lc = (tid & 7) * 4;             // col 0,4,...,28

    for (int t = 0; t < T_; t++) {
        float acc[5][4];
#pragma unroll
        for (int g = 0; g < 5; g++)
#pragma unroll
            for (int i = 0; i < 4; i++) acc[g][i] = 0.f;

        if (t > 0) {
            const float* __restrict__ hprev = g_H + (size_t)(t - 1) * B_ * H_;

            // prologue: chunk 0 straight to smem buffer 0
            {
                float4 v0 = *reinterpret_cast<const float4*>(hprev + (size_t)(b0 + lr) * H_ + lc);
                float4 v1 = *reinterpret_cast<const float4*>(hprev + (size_t)(b0 + lr + 32) * H_ + lc);
                float* A0 = As;
#pragma unroll
                for (int i = 0; i < 4; i++) {
                    A0[(lc + i) * AS_W + lr]      = (&v0.x)[i];
                    A0[(lc + i) * AS_W + lr + 32] = (&v1.x)[i];
                }
            }
            __syncthreads();

            for (int kc = 0; kc < 16; kc++) {
                float4 v0, v1;
                if (kc < 15) {
                    const float* hp = hprev + (kc + 1) * 32;
                    v0 = *reinterpret_cast<const float4*>(hp + (size_t)(b0 + lr) * H_ + lc);
                    v1 = *reinterpret_cast<const float4*>(hp + (size_t)(b0 + lr + 32) * H_ + lc);
                }

                const float* Ab = As + (kc & 1) * AS_ELE + trow * 4;
                const float* Wk = Wsm + (kc * 32) * W_COLS + tcol;
#pragma unroll 8
                for (int kk = 0; kk < 32; kk++) {
                    float4 a = *reinterpret_cast<const float4*>(Ab + kk * AS_W);
                    const float* wr = Wk + kk * W_COLS;
                    float w0 = wr[0], w1 = wr[16], w2 = wr[32], w3 = wr[48], w4 = wr[64];
                    acc[0][0] = fmaf(a.x, w0, acc[0][0]);
                    acc[0][1] = fmaf(a.y, w0, acc[0][1]);
                    acc[0][2] = fmaf(a.z, w0, acc[0][2]);
                    acc[0][3] = fmaf(a.w, w0, acc[0][3]);
                    acc[1][0] = fmaf(a.x, w1, acc[1][0]);
                    acc[1][1] = fmaf(a.y, w1, acc[1][1]);
                    acc[1][2] = fmaf(a.z, w1, acc[1][2]);
                    acc[1][3] = fmaf(a.w, w1, acc[1][3]);
                    acc[2][0] = fmaf(a.x, w2, acc[2][0]);
                    acc[2][1] = fmaf(a.y, w2, acc[2][1]);
                    acc[2][2] = fmaf(a.z, w2, acc[2][2]);
                    acc[2][3] = fmaf(a.w, w2, acc[2][3]);
                    acc[3][0] = fmaf(a.x, w3, acc[3][0]);
                    acc[3][1] = fmaf(a.y, w3, acc[3][1]);
                    acc[3][2] = fmaf(a.z, w3, acc[3][2]);
                    acc[3][3] = fmaf(a.w, w3, acc[3][3]);
                    acc[4][0] = fmaf(a.x, w4, acc[4][0]);
                    acc[4][1] = fmaf(a.y, w4, acc[4][1]);
                    acc[4][2] = fmaf(a.z, w4, acc[4][2]);
                    acc[4][3] = fmaf(a.w, w4, acc[4][3]);
                }

                if (kc < 15) {
                    float* An = As + ((kc + 1) & 1) * AS_ELE;
#pragma unroll
                    for (int i = 0; i < 4; i++) {
                        An[(lc + i) * AS_W + lr]      = (&v0.x)[i];
                        An[(lc + i) * AS_W + lr + 32] = (&v1.x)[i];
                    }
                }
                __syncthreads();
            }
        }

        // ---- epilogue: gates + cell + highway + dropout
        float* __restrict__ hout = g_H + (size_t)t * B_ * H_;
        const float* __restrict__ piB = g_PI + (size_t)t * B_ * SIXH_;
#pragma unroll
        for (int i = 0; i < 4; i++) {
            int b = b0 + trow * 4 + i;
            const float* pi = piB + (size_t)b * SIXH_;
            float ig = sigmoidf_(pi[0 * H_ + n] + acc[0][i] + bsr[0]);
            float fg = sigmoidf_(pi[1 * H_ + n] + acc[1][i] + bsr[1]);
            float mi = tanhf   (pi[2 * H_ + n] + acc[2][i] + bsr[2]);
            float og = sigmoidf_(pi[3 * H_ + n] + acc[3][i] + bsr[3]);
            float hg = sigmoidf_(pi[4 * H_ + n] + acc[4][i] + bsr[4]);

            float c_new = ig * mi + fg * c_reg[i];
            float out   = og * tanhf(c_new);
            out = hg * out + (1.f - hg) * pi[5 * H_ + n];
            out *= m_reg[i];
            c_reg[i] = c_new;
            hout[(size_t)b * H_ + n] = out;
        }

        // ---- grid barrier: h(t) visible to all before step t+1
        if (t < T_ - 1) {
            __syncthreads();
            if (tid == 0) {
                __threadfence();
                unsigned prev = atomicAdd(&g_arrive, 1);
                if (prev == NCTA_ - 1) {
                    g_arrive = 0;
                    __threadfence();
                    atomicAdd(&g_gen, 1);
                } else {
                    unsigned target = base + (unsigned)t + 1u;
                    unsigned v;
                    do {
                        asm volatile("ld.acquire.gpu.global.u32 %0, [%1];"
                                     : "=r"(v) : "l"(&g_gen));
                    } while (v - base < target - base);
                }
            }
            __syncthreads();
        }
    }
}

// ---------------------------------------------------------------------------
// kernel_launch
// Input order: x, labels, embed, Wi, bi, Ws, bs, Wo, bo, mask
// ---------------------------------------------------------------------------
extern "C" void kernel_launch(void* const* d_in, const int* in_sizes, int n_in,
                              void* d_out, int out_size) {
    const float* x      = (const float*)d_in[0];
    const int*   labels = (const int*)  d_in[1];
    const float* embed  = (const float*)d_in[2];
    const float* Wi     = (const float*)d_in[3];
    const float* bi     = (const float*)d_in[4];
    const float* Ws     = (const float*)d_in[5];
    const float* bs     = (const float*)d_in[6];
    const float* Wo     = (const float*)d_in[7];
    const float* bo     = (const float*)d_in[8];
    const float* mask   = (const float*)d_in[9];
    float* out = (float*)d_out;

    float *ti, *pi, *hall;
    cudaGetSymbolAddress((void**)&ti,   g_TI);
    cudaGetSymbolAddress((void**)&pi,   g_PI);
    cudaGetSymbolAddress((void**)&hall, g_H);

    // 1) concat(x, embed[labels]) -> TI
    {
        int total = T_ * B_ * (KIN_ / 4);
        k_concat<<<(total + 255) / 256, 256>>>(x, labels, embed);
    }

    // 2) PI = TI @ Wi^T + bi   (16384 x 3072 x 1024)
    {
        dim3 grid(SIXH_ / 128, (T_ * B_) / 128);
        k_sgemm<<<grid, 256>>>(T_ * B_, SIXH_, KIN_, ti, Wi, bi, pi);
    }

    // 3) persistent recurrence (all 64 steps, one launch)
    {
        const int smem_bytes = (512 * W_COLS + 2 * AS_ELE) * (int)sizeof(float);
        cudaFuncSetAttribute(k_recur, cudaFuncAttributeMaxDynamicSharedMemorySize, smem_bytes);
        k_recur<<<NCTA_, 256, smem_bytes>>>(Ws, bs, mask);
    }

    // 4) OUT = H_all @ Wo^T + bo   (16384 x 151 x 512)
    {
        dim3 grid((NC_ + 127) / 128, (T_ * B_) / 128);
        k_sgemm<<<grid, 256>>>(T_ * B_, NC_, H_, hall, Wo, bo, out);
    }
}

// round 4
// speedup vs baseline: 1.8269x; 1.4984x over previous
#include <cuda_runtime.h>
#include <cuda_bf16.h>
#include <cstdint>
#include <math.h>

// Problem constants
#define T_    64
#define B_    256
#define FEAT_ 924
#define H_    512
#define NC_   151
#define ED_   100
#define KIN_  (FEAT_ + ED_)   // 1024
#define SIXH_ (6 * H_)        // 3072
#define M_TOT (T_ * B_)       // 16384

#define NCTA_  128            // persistent recurrence grid
#define NTILE_ 16
#define BTILE_ 64

// ---------------------------------------------------------------------------
// Scratch (static device globals)
// ---------------------------------------------------------------------------
__device__ __nv_bfloat16 g_TIhi[(size_t)M_TOT * KIN_];
__device__ __nv_bfloat16 g_TIlo[(size_t)M_TOT * KIN_];
__device__ __nv_bfloat16 g_Wihi[(size_t)SIXH_ * KIN_];
__device__ __nv_bfloat16 g_Wilo[(size_t)SIXH_ * KIN_];
__device__ float g_PI[(size_t)M_TOT * SIXH_];
__device__ float g_H [(size_t)M_TOT * H_];

__device__ unsigned g_arrive = 0;
__device__ unsigned g_gen    = 0;

// ---------------------------------------------------------------------------
// PTX helpers (all compute_103-safe: mma.sync / ldmatrix / cp.async)
// ---------------------------------------------------------------------------
__device__ __forceinline__ uint32_t smem_u32(const void* p) {
    uint32_t a;
    asm("{ .reg .u64 t; cvta.to.shared.u64 t, %1; cvt.u32.u64 %0, t; }" : "=r"(a) : "l"(p));
    return a;
}

#define CP_ASYNC16(dst, src) \
    asm volatile("cp.async.cg.shared.global [%0], [%1], 16;" :: "r"(dst), "l"(src) : "memory")
#define CP_COMMIT() asm volatile("cp.async.commit_group;" ::: "memory")
#define CP_WAIT(n)  asm volatile("cp.async.wait_group %0;" :: "n"(n) : "memory")

__device__ __forceinline__ void ldsm4(uint32_t* r, uint32_t addr) {
    asm volatile("ldmatrix.sync.aligned.m8n8.x4.shared.b16 {%0,%1,%2,%3}, [%4];"
                 : "=r"(r[0]), "=r"(r[1]), "=r"(r[2]), "=r"(r[3]) : "r"(addr));
}

__device__ __forceinline__ void mma16816(float* d, const uint32_t* a, const uint32_t* b) {
    asm volatile(
        "mma.sync.aligned.m16n8k16.row.col.f32.bf16.bf16.f32 "
        "{%0,%1,%2,%3}, {%4,%5,%6,%7}, {%8,%9}, {%0,%1,%2,%3};"
        : "+f"(d[0]), "+f"(d[1]), "+f"(d[2]), "+f"(d[3])
        : "r"(a[0]), "r"(a[1]), "r"(a[2]), "r"(a[3]), "r"(b[0]), "r"(b[1]));
}

// ---------------------------------------------------------------------------
// Split helpers: fp32 -> (bf16 hi, bf16 lo)
// ---------------------------------------------------------------------------
union BF4 { __nv_bfloat16 b[4]; uint2 u; };

__device__ __forceinline__ void split4(const float4 v, uint2* hi, uint2* lo) {
    BF4 Hh, Ll;
#pragma unroll
    for (int i = 0; i < 4; i++) {
        float f = (&v.x)[i];
        __nv_bfloat16 h = __float2bfloat16_rn(f);
        Hh.b[i] = h;
        Ll.b[i] = __float2bfloat16_rn(f - __bfloat162float(h));
    }
    *hi = Hh.u; *lo = Ll.u;
}

__global__ void k_concat_split(const float* __restrict__ x,
                               const int*   __restrict__ labels,
                               const float* __restrict__ embed) {
    const int C4 = KIN_ / 4;
    int idx = blockIdx.x * blockDim.x + threadIdx.x;
    if (idx >= M_TOT * C4) return;
    int row = idx / C4;
    int c   = (idx % C4) * 4;
    float4 v;
    if (c < FEAT_) {
        v = *reinterpret_cast<const float4*>(x + (size_t)row * FEAT_ + c);
    } else {
        int lab = labels[row];
        v = *reinterpret_cast<const float4*>(embed + (size_t)lab * ED_ + (c - FEAT_));
    }
    uint2 hi, lo;
    split4(v, &hi, &lo);
    *reinterpret_cast<uint2*>(g_TIhi + (size_t)row * KIN_ + c) = hi;
    *reinterpret_cast<uint2*>(g_TIlo + (size_t)row * KIN_ + c) = lo;
}

__global__ void k_split_w(const float* __restrict__ Wi) {
    int idx = blockIdx.x * blockDim.x + threadIdx.x;
    if (idx >= SIXH_ * (KIN_ / 4)) return;
    size_t off = (size_t)idx * 4;
    float4 v = *reinterpret_cast<const float4*>(Wi + off);
    uint2 hi, lo;
    split4(v, &hi, &lo);
    *reinterpret_cast<uint2*>(g_Wihi + off) = hi;
    *reinterpret_cast<uint2*>(g_Wilo + off) = lo;
}

// ---------------------------------------------------------------------------
// GEMM1 via mma.sync bf16 3-term split.
//   C[M,N] = A@B^T + bias,  A=(M,K) hi/lo bf16, B=(N,K) hi/lo bf16.
//   CTA 128x128, BK=32, 8 warps (2M x 4N), warp tile 64x32.
//   smem row stride 80B -> ldmatrix conflict-free; cp.async double buffer.
// ---------------------------------------------------------------------------
#define BK_      32
#define NCH_     (KIN_ / BK_)          // 32 chunks
#define ROWB_    80                    // padded row stride (bytes)
#define TILEB_   (128 * ROWB_)         // 10240 bytes per tile
#define STAGEB_  (4 * TILEB_)          // Ahi, Alo, Bhi, Blo
#define SMOFF_   1024                  // tiles start (bias below)

__global__ __launch_bounds__(256)
void k_mma1(const float* __restrict__ bi) {
    extern __shared__ char smem[];
    const uint32_t sb = smem_u32(smem);
    const int tid = threadIdx.x;
    const int wid = tid >> 5;
    const int lid = tid & 31;

    const int mt = blockIdx.x / (SIXH_ / 128);   // 0..127
    const int nt = blockIdx.x % (SIXH_ / 128);   // 0..23
    const int m0 = mt * 128;
    const int n0 = nt * 128;

    float* s_bias = reinterpret_cast<float*>(smem);
    if (tid < 128) s_bias[tid] = bi[n0 + tid];

    const __nv_bfloat16* __restrict__ Ahi = g_TIhi + (size_t)m0 * KIN_;
    const __nv_bfloat16* __restrict__ Alo = g_TIlo + (size_t)m0 * KIN_;
    const __nv_bfloat16* __restrict__ Bhi = g_Wihi + (size_t)n0 * KIN_;
    const __nv_bfloat16* __restrict__ Blo = g_Wilo + (size_t)n0 * KIN_;

    // loader: per tile 128 rows x 2 lines of 16B; 2 lines per thread
    const int lr0 = tid >> 2;            // e = tid      : row
    const int lc0 = (tid & 3);           //               : 16B col
    const int lr1 = (tid + 256) >> 2;    // e = tid + 256
    const int lc1 = ((tid + 256) & 3);

    auto load_stage = [&](int ch, int stage) {
        const int k0 = ch * BK_;
        const uint32_t base = sb + SMOFF_ + stage * STAGEB_;
        const __nv_bfloat16* srcs[4] = {Ahi, Alo, Bhi, Blo};
#pragma unroll
        for (int tl = 0; tl < 4; tl++) {
            const __nv_bfloat16* s = srcs[tl];
            uint32_t tb = base + tl * TILEB_;
            CP_ASYNC16(tb + lr0 * ROWB_ + lc0 * 16, s + (size_t)lr0 * KIN_ + k0 + lc0 * 8);
            CP_ASYNC16(tb + lr1 * ROWB_ + lc1 * 16, s + (size_t)lr1 * KIN_ + k0 + lc1 * 8);
        }
        CP_COMMIT();
    };

    // warp coords
    const int wm = wid >> 2;             // 0..1 (64 rows each)
    const int wn = wid & 3;              // 0..3 (32 cols each)
    const int lrow = lid & 15;           // ldmatrix row lane
    const int lhalf = lid >> 4;          // ldmatrix 16B-col lane

    float acc[4][4][4];                  // [mf][nfidx][reg]
#pragma unroll
    for (int i = 0; i < 4; i++)
#pragma unroll
        for (int j = 0; j < 4; j++)
#pragma unroll
            for (int r = 0; r < 4; r++) acc[i][j][r] = 0.f;

    load_stage(0, 0);

    for (int ch = 0; ch < NCH_; ch++) {
        const int stage = ch & 1;
        if (ch + 1 < NCH_) {
            load_stage(ch + 1, stage ^ 1);
            CP_WAIT(1);
        } else {
            CP_WAIT(0);
        }
        __syncthreads();

        const uint32_t base = sb + SMOFF_ + stage * STAGEB_;
        const uint32_t aHi = base + 0 * TILEB_;
        const uint32_t aLo = base + 1 * TILEB_;
        const uint32_t bHi = base + 2 * TILEB_;
        const uint32_t bLo = base + 3 * TILEB_;

#pragma unroll
        for (int ks = 0; ks < 2; ks++) {
            const uint32_t koff = ks * 32 + lhalf * 16;   // k-step 16 bf16 = 32B

            uint32_t a_hi[4][4], a_lo[4][4];
#pragma unroll
            for (int mf = 0; mf < 4; mf++) {
                uint32_t roff = (uint32_t)(wm * 64 + mf * 16 + lrow) * ROWB_ + koff;
                ldsm4(a_hi[mf], aHi + roff);
                ldsm4(a_lo[mf], aLo + roff);
            }
            uint32_t b_hi[2][4], b_lo[2][4];
#pragma unroll
            for (int np = 0; np < 2; np++) {
                uint32_t roff = (uint32_t)(wn * 32 + np * 16 + lrow) * ROWB_ + koff;
                ldsm4(b_hi[np], bHi + roff);
                ldsm4(b_lo[np], bLo + roff);
            }

            // b-frag extraction: ldsm4 regs {n0-7/k0-7, n8-15/k0-7, n0-7/k8-15, n8-15/k8-15}
            // nfrag (np*2+q): b = {regs[q], regs[q+2]}
#pragma unroll
            for (int mf = 0; mf < 4; mf++) {
#pragma unroll
                for (int np = 0; np < 2; np++) {
#pragma unroll
                    for (int q = 0; q < 2; q++) {
                        uint32_t bh[2] = {b_hi[np][q], b_hi[np][q + 2]};
                        uint32_t bl[2] = {b_lo[np][q], b_lo[np][q + 2]};
                        float* d = acc[mf][np * 2 + q];
                        mma16816(d, a_hi[mf], bh);
                        mma16816(d, a_hi[mf], bl);
                        mma16816(d, a_lo[mf], bh);
                    }
                }
            }
        }
        __syncthreads();
    }

    // epilogue: d0,d1 -> (row, col..col+1); d2,d3 -> (row+8, col..col+1)
    const int trow = lid >> 2;
    const int tcol2 = (lid & 3) * 2;
#pragma unroll
    for (int mf = 0; mf < 4; mf++) {
        int m = m0 + wm * 64 + mf * 16 + trow;
        float* __restrict__ o0 = g_PI + (size_t)m * SIXH_ + n0;
        float* __restrict__ o1 = g_PI + (size_t)(m + 8) * SIXH_ + n0;
#pragma unroll
        for (int nf = 0; nf < 4; nf++) {
            int cn = wn * 32 + nf * 8 + tcol2;
            float b0 = s_bias[cn], b1 = s_bias[cn + 1];
            float2 v0 = make_float2(acc[mf][nf][0] + b0, acc[mf][nf][1] + b1);
            float2 v1 = make_float2(acc[mf][nf][2] + b0, acc[mf][nf][3] + b1);
            *reinterpret_cast<float2*>(o0 + cn) = v0;
            *reinterpret_cast<float2*>(o1 + cn) = v1;
        }
    }
}

// ---------------------------------------------------------------------------
// Generic SGEMM (output GEMM): C = A @ B^T + bias
// ---------------------------------------------------------------------------
__global__ __launch_bounds__(256)
void k_sgemm(int M, int N, int K,
             const float* __restrict__ A,
             const float* __restrict__ B,
             const float* __restrict__ bias,
             float* __restrict__ C) {
    constexpr int BM = 128, BN = 128, BK = 8, TM = 8, TN = 8;
    __shared__ float As[BK][BM];
    __shared__ float Bs[BK][BN];

    const int tid = threadIdx.x;
    const int m0  = blockIdx.y * BM;
    const int n0  = blockIdx.x * BN;
    const int trow = tid / (BN / TN);
    const int tcol = tid % (BN / TN);
    const int a_row = tid >> 1;
    const int a_col = (tid & 1) * 4;

    float acc[TM][TN];
#pragma unroll
    for (int i = 0; i < TM; i++)
#pragma unroll
        for (int j = 0; j < TN; j++) acc[i][j] = 0.f;

    for (int k0 = 0; k0 < K; k0 += BK) {
        {
            int gm = m0 + a_row;
            float4 v = make_float4(0.f, 0.f, 0.f, 0.f);
            if (gm < M) v = *reinterpret_cast<const float4*>(A + (size_t)gm * K + k0 + a_col);
            As[a_col + 0][a_row] = v.x;
            As[a_col + 1][a_row] = v.y;
            As[a_col + 2][a_row] = v.z;
            As[a_col + 3][a_row] = v.w;
        }
        {
            int gn = n0 + a_row;
            float4 v = make_float4(0.f, 0.f, 0.f, 0.f);
            if (gn < N) v = *reinterpret_cast<const float4*>(B + (size_t)gn * K + k0 + a_col);
            Bs[a_col + 0][a_row] = v.x;
            Bs[a_col + 1][a_row] = v.y;
            Bs[a_col + 2][a_row] = v.z;
            Bs[a_col + 3][a_row] = v.w;
        }
        __syncthreads();

#pragma unroll
        for (int kk = 0; kk < BK; kk++) {
            float a[TM], b[TN];
            *reinterpret_cast<float4*>(&a[0]) = *reinterpret_cast<const float4*>(&As[kk][trow * TM + 0]);
            *reinterpret_cast<float4*>(&a[4]) = *reinterpret_cast<const float4*>(&As[kk][trow * TM + 4]);
            *reinterpret_cast<float4*>(&b[0]) = *reinterpret_cast<const float4*>(&Bs[kk][tcol * TN + 0]);
            *reinterpret_cast<float4*>(&b[4]) = *reinterpret_cast<const float4*>(&Bs[kk][tcol * TN + 4]);
#pragma unroll
            for (int i = 0; i < TM; i++)
#pragma unroll
                for (int j = 0; j < TN; j++)
                    acc[i][j] = fmaf(a[i], b[j], acc[i][j]);
        }
        __syncthreads();
    }

#pragma unroll
    for (int i = 0; i < TM; i++) {
        int gm = m0 + trow * TM + i;
        if (gm >= M) continue;
#pragma unroll
        for (int j = 0; j < TN; j++) {
            int gn = n0 + tcol * TN + j;
            if (gn < N) C[(size_t)gm * N + gn] = acc[i][j] + bias[gn];
        }
    }
}

// ---------------------------------------------------------------------------
// Persistent recurrence kernel (unchanged, known-correct)
// ---------------------------------------------------------------------------
__device__ __forceinline__ float sigmoidf_(float x) {
    return 1.f / (1.f + __expf(-x));
}

#define W_COLS 80
#define AS_W   68
#define AS_ELE (32 * AS_W)

__global__ __launch_bounds__(256, 1)
void k_recur(const float* __restrict__ Ws,
             const float* __restrict__ bs,
             const float* __restrict__ mask)
{
    extern __shared__ float smemf[];
    float* Wsm = smemf;
    float* As  = smemf + 512 * W_COLS;

    const int tid  = threadIdx.x;
    const int nt   = blockIdx.x & 31;
    const int bt   = blockIdx.x >> 5;
    const int n0   = nt * NTILE_;
    const int b0   = bt * BTILE_;

    const int trow = tid >> 4;
    const int tcol = tid & 15;
    const int n    = n0 + tcol;

    __shared__ unsigned s_base;
    if (tid == 0) {
        unsigned v;
        asm volatile("ld.acquire.gpu.global.u32 %0, [%1];" : "=r"(v) : "l"(&g_gen));
        s_base = v;
    }

    for (int s = tid; s < W_COLS * (H_ / 4); s += 256) {
        int k4 = s / W_COLS;
        int vr = s % W_COLS;
        int g  = vr >> 4, j = vr & 15;
        float4 v = *reinterpret_cast<const float4*>(
            Ws + (size_t)(g * H_ + n0 + j) * H_ + k4 * 4);
        Wsm[(k4 * 4 + 0) * W_COLS + vr] = v.x;
        Wsm[(k4 * 4 + 1) * W_COLS + vr] = v.y;
        Wsm[(k4 * 4 + 2) * W_COLS + vr] = v.z;
        Wsm[(k4 * 4 + 3) * W_COLS + vr] = v.w;
    }

    float c_reg[4] = {0.f, 0.f, 0.f, 0.f};
    float m_reg[4], bsr[5];
#pragma unroll
    for (int i = 0; i < 4; i++) m_reg[i] = mask[(size_t)(b0 + trow * 4 + i) * H_ + n];
#pragma unroll
    for (int g = 0; g < 5; g++) bsr[g] = bs[g * H_ + n];

    __syncthreads();
    const unsigned base = s_base;

    const int lr = tid >> 3;
    const int lc = (tid & 7) * 4;

    for (int t = 0; t < T_; t++) {
        float acc[5][4];
#pragma unroll
        for (int g = 0; g < 5; g++)
#pragma unroll
            for (int i = 0; i < 4; i++) acc[g][i] = 0.f;

        if (t > 0) {
            const float* __restrict__ hprev = g_H + (size_t)(t - 1) * B_ * H_;
            {
                float4 v0 = *reinterpret_cast<const float4*>(hprev + (size_t)(b0 + lr) * H_ + lc);
                float4 v1 = *reinterpret_cast<const float4*>(hprev + (size_t)(b0 + lr + 32) * H_ + lc);
                float* A0 = As;
#pragma unroll
                for (int i = 0; i < 4; i++) {
                    A0[(lc + i) * AS_W + lr]      = (&v0.x)[i];
                    A0[(lc + i) * AS_W + lr + 32] = (&v1.x)[i];
                }
            }
            __syncthreads();

            for (int kc = 0; kc < 16; kc++) {
                float4 v0, v1;
                if (kc < 15) {
                    const float* hp = hprev + (kc + 1) * 32;
                    v0 = *reinterpret_cast<const float4*>(hp + (size_t)(b0 + lr) * H_ + lc);
                    v1 = *reinterpret_cast<const float4*>(hp + (size_t)(b0 + lr + 32) * H_ + lc);
                }

                const float* Ab = As + (kc & 1) * AS_ELE + trow * 4;
                const float* Wk = Wsm + (kc * 32) * W_COLS + tcol;
#pragma unroll 8
                for (int kk = 0; kk < 32; kk++) {
                    float4 a = *reinterpret_cast<const float4*>(Ab + kk * AS_W);
                    const float* wr = Wk + kk * W_COLS;
                    float w0 = wr[0], w1 = wr[16], w2 = wr[32], w3 = wr[48], w4 = wr[64];
                    acc[0][0] = fmaf(a.x, w0, acc[0][0]);
                    acc[0][1] = fmaf(a.y, w0, acc[0][1]);
                    acc[0][2] = fmaf(a.z, w0, acc[0][2]);
                    acc[0][3] = fmaf(a.w, w0, acc[0][3]);
                    acc[1][0] = fmaf(a.x, w1, acc[1][0]);
                    acc[1][1] = fmaf(a.y, w1, acc[1][1]);
                    acc[1][2] = fmaf(a.z, w1, acc[1][2]);
                    acc[1][3] = fmaf(a.w, w1, acc[1][3]);
                    acc[2][0] = fmaf(a.x, w2, acc[2][0]);
                    acc[2][1] = fmaf(a.y, w2, acc[2][1]);
                    acc[2][2] = fmaf(a.z, w2, acc[2][2]);
                    acc[2][3] = fmaf(a.w, w2, acc[2][3]);
                    acc[3][0] = fmaf(a.x, w3, acc[3][0]);
                    acc[3][1] = fmaf(a.y, w3, acc[3][1]);
                    acc[3][2] = fmaf(a.z, w3, acc[3][2]);
                    acc[3][3] = fmaf(a.w, w3, acc[3][3]);
                    acc[4][0] = fmaf(a.x, w4, acc[4][0]);
                    acc[4][1] = fmaf(a.y, w4, acc[4][1]);
                    acc[4][2] = fmaf(a.z, w4, acc[4][2]);
                    acc[4][3] = fmaf(a.w, w4, acc[4][3]);
                }

                if (kc < 15) {
                    float* An = As + ((kc + 1) & 1) * AS_ELE;
#pragma unroll
                    for (int i = 0; i < 4; i++) {
                        An[(lc + i) * AS_W + lr]      = (&v0.x)[i];
                        An[(lc + i) * AS_W + lr + 32] = (&v1.x)[i];
                    }
                }
                __syncthreads();
            }
        }

        float* __restrict__ hout = g_H + (size_t)t * B_ * H_;
        const float* __restrict__ piB = g_PI + (size_t)t * B_ * SIXH_;
#pragma unroll
        for (int i = 0; i < 4; i++) {
            int b = b0 + trow * 4 + i;
            const float* pi = piB + (size_t)b * SIXH_;
            float ig = sigmoidf_(pi[0 * H_ + n] + acc[0][i] + bsr[0]);
            float fg = sigmoidf_(pi[1 * H_ + n] + acc[1][i] + bsr[1]);
            float mi = tanhf   (pi[2 * H_ + n] + acc[2][i] + bsr[2]);
            float og = sigmoidf_(pi[3 * H_ + n] + acc[3][i] + bsr[3]);
            float hg = sigmoidf_(pi[4 * H_ + n] + acc[4][i] + bsr[4]);

            float c_new = ig * mi + fg * c_reg[i];
            float out   = og * tanhf(c_new);
            out = hg * out + (1.f - hg) * pi[5 * H_ + n];
            out *= m_reg[i];
            c_reg[i] = c_new;
            hout[(size_t)b * H_ + n] = out;
        }

        if (t < T_ - 1) {
            __syncthreads();
            if (tid == 0) {
                __threadfence();
                unsigned prev = atomicAdd(&g_arrive, 1);
                if (prev == NCTA_ - 1) {
                    g_arrive = 0;
                    __threadfence();
                    atomicAdd(&g_gen, 1);
                } else {
                    unsigned target = base + (unsigned)t + 1u;
                    unsigned v;
                    do {
                        asm volatile("ld.acquire.gpu.global.u32 %0, [%1];"
                                     : "=r"(v) : "l"(&g_gen));
                    } while (v - base < target - base);
                }
            }
            __syncthreads();
        }
    }
}

// ---------------------------------------------------------------------------
// kernel_launch
// Input order: x, labels, embed, Wi, bi, Ws, bs, Wo, bo, mask
// ---------------------------------------------------------------------------
extern "C" void kernel_launch(void* const* d_in, const int* in_sizes, int n_in,
                              void* d_out, int out_size) {
    const float* x      = (const float*)d_in[0];
    const int*   labels = (const int*)  d_in[1];
    const float* embed  = (const float*)d_in[2];
    const float* Wi     = (const float*)d_in[3];
    const float* bi     = (const float*)d_in[4];
    const float* Ws     = (const float*)d_in[5];
    const float* bs     = (const float*)d_in[6];
    const float* Wo     = (const float*)d_in[7];
    const float* bo     = (const float*)d_in[8];
    const float* mask   = (const float*)d_in[9];
    float* out = (float*)d_out;

    float* hall;
    cudaGetSymbolAddress((void**)&hall, g_H);

    // 1) split Wi into bf16 hi/lo
    {
        int total = SIXH_ * (KIN_ / 4);
        k_split_w<<<(total + 255) / 256, 256>>>(Wi);
    }
    // 2) concat + split TI into bf16 hi/lo
    {
        int total = M_TOT * (KIN_ / 4);
        k_concat_split<<<(total + 255) / 256, 256>>>(x, labels, embed);
    }
    // 3) PI = TI @ Wi^T + bi via mma.sync bf16 3-term split
    {
        const int smem_bytes = SMOFF_ + 2 * STAGEB_;   // 1024 + 80KB
        cudaFuncSetAttribute(k_mma1, cudaFuncAttributeMaxDynamicSharedMemorySize, smem_bytes);
        dim3 grid((M_TOT / 128) * (SIXH_ / 128));      // 3072
        k_mma1<<<grid, 256, smem_bytes>>>(bi);
    }
    // 4) persistent recurrence
    {
        const int smem_bytes = (512 * W_COLS + 2 * AS_ELE) * (int)sizeof(float);
        cudaFuncSetAttribute(k_recur, cudaFuncAttributeMaxDynamicSharedMemorySize, smem_bytes);
        k_recur<<<NCTA_, 256, smem_bytes>>>(Ws, bs, mask);
    }
    // 5) OUT = H_all @ Wo^T + bo
    {
        dim3 grid((NC_ + 127) / 128, M_TOT / 128);
        k_sgemm<<<grid, 256>>>(M_TOT, NC_, H_, hall, Wo, bo, out);
    }
}

// round 5
// speedup vs baseline: 3.1002x; 1.6970x over previous
#include <cuda_runtime.h>
#include <cuda_bf16.h>
#include <cstdint>
#include <math.h>

// Problem constants
#define T_    64
#define B_    256
#define FEAT_ 924
#define H_    512
#define NC_   151
#define ED_   100
#define KIN_  (FEAT_ + ED_)   // 1024
#define SIXH_ (6 * H_)        // 3072
#define M_TOT (T_ * B_)       // 16384

#define NCTA_  128            // persistent recurrence grid

// ---------------------------------------------------------------------------
// Scratch (static device globals)
// ---------------------------------------------------------------------------
__device__ __nv_bfloat16 g_TIhi[(size_t)M_TOT * KIN_];
__device__ __nv_bfloat16 g_TIlo[(size_t)M_TOT * KIN_];
__device__ __nv_bfloat16 g_Wihi[(size_t)SIXH_ * KIN_];
__device__ __nv_bfloat16 g_Wilo[(size_t)SIXH_ * KIN_];
__device__ float g_PI[(size_t)M_TOT * SIXH_];
__device__ float g_H [(size_t)M_TOT * H_];
__device__ __nv_bfloat16 g_Hhi[2 * B_ * H_];   // double-buffered bf16 h
__device__ __nv_bfloat16 g_Hlo[2 * B_ * H_];

__device__ unsigned g_arrive = 0;
__device__ unsigned g_gen    = 0;

// ---------------------------------------------------------------------------
// PTX helpers (compute_103-safe: mma.sync / ldmatrix / cp.async)
// ---------------------------------------------------------------------------
__device__ __forceinline__ uint32_t smem_u32(const void* p) {
    uint32_t a;
    asm("{ .reg .u64 t; cvta.to.shared.u64 t, %1; cvt.u32.u64 %0, t; }" : "=r"(a) : "l"(p));
    return a;
}

#define CP_ASYNC16(dst, src) \
    asm volatile("cp.async.cg.shared.global [%0], [%1], 16;" :: "r"(dst), "l"(src) : "memory")
#define CP_COMMIT() asm volatile("cp.async.commit_group;" ::: "memory")
#define CP_WAIT(n)  asm volatile("cp.async.wait_group %0;" :: "n"(n) : "memory")

__device__ __forceinline__ void ldsm4(uint32_t* r, uint32_t addr) {
    asm volatile("ldmatrix.sync.aligned.m8n8.x4.shared.b16 {%0,%1,%2,%3}, [%4];"
                 : "=r"(r[0]), "=r"(r[1]), "=r"(r[2]), "=r"(r[3]) : "r"(addr));
}

__device__ __forceinline__ void mma16816(float* d, const uint32_t* a, const uint32_t* b) {
    asm volatile(
        "mma.sync.aligned.m16n8k16.row.col.f32.bf16.bf16.f32 "
        "{%0,%1,%2,%3}, {%4,%5,%6,%7}, {%8,%9}, {%0,%1,%2,%3};"
        : "+f"(d[0]), "+f"(d[1]), "+f"(d[2]), "+f"(d[3])
        : "r"(a[0]), "r"(a[1]), "r"(a[2]), "r"(a[3]), "r"(b[0]), "r"(b[1]));
}

// ---------------------------------------------------------------------------
// Split helpers: fp32 -> (bf16 hi, bf16 lo)
// ---------------------------------------------------------------------------
union BF4 { __nv_bfloat16 b[4]; uint2 u; };

__device__ __forceinline__ void split4(const float4 v, uint2* hi, uint2* lo) {
    BF4 Hh, Ll;
#pragma unroll
    for (int i = 0; i < 4; i++) {
        float f = (&v.x)[i];
        __nv_bfloat16 h = __float2bfloat16_rn(f);
        Hh.b[i] = h;
        Ll.b[i] = __float2bfloat16_rn(f - __bfloat162float(h));
    }
    *hi = Hh.u; *lo = Ll.u;
}

__global__ void k_concat_split(const float* __restrict__ x,
                               const int*   __restrict__ labels,
                               const float* __restrict__ embed) {
    const int C4 = KIN_ / 4;
    int idx = blockIdx.x * blockDim.x + threadIdx.x;
    if (idx >= M_TOT * C4) return;
    int row = idx / C4;
    int c   = (idx % C4) * 4;
    float4 v;
    if (c < FEAT_) {
        v = *reinterpret_cast<const float4*>(x + (size_t)row * FEAT_ + c);
    } else {
        int lab = labels[row];
        v = *reinterpret_cast<const float4*>(embed + (size_t)lab * ED_ + (c - FEAT_));
    }
    uint2 hi, lo;
    split4(v, &hi, &lo);
    *reinterpret_cast<uint2*>(g_TIhi + (size_t)row * KIN_ + c) = hi;
    *reinterpret_cast<uint2*>(g_TIlo + (size_t)row * KIN_ + c) = lo;
}

__global__ void k_split_w(const float* __restrict__ Wi) {
    int idx = blockIdx.x * blockDim.x + threadIdx.x;
    if (idx >= SIXH_ * (KIN_ / 4)) return;
    size_t off = (size_t)idx * 4;
    float4 v = *reinterpret_cast<const float4*>(Wi + off);
    uint2 hi, lo;
    split4(v, &hi, &lo);
    *reinterpret_cast<uint2*>(g_Wihi + off) = hi;
    *reinterpret_cast<uint2*>(g_Wilo + off) = lo;
}

// ---------------------------------------------------------------------------
// GEMM1 via mma.sync bf16 3-term split (unchanged from R4, known-good)
// ---------------------------------------------------------------------------
#define BK_      32
#define NCH_     (KIN_ / BK_)
#define ROWB_    80
#define TILEB_   (128 * ROWB_)
#define STAGEB_  (4 * TILEB_)
#define SMOFF_   1024

__global__ __launch_bounds__(256)
void k_mma1(const float* __restrict__ bi) {
    extern __shared__ char smem[];
    const uint32_t sb = smem_u32(smem);
    const int tid = threadIdx.x;
    const int wid = tid >> 5;
    const int lid = tid & 31;

    const int mt = blockIdx.x / (SIXH_ / 128);
    const int nt = blockIdx.x % (SIXH_ / 128);
    const int m0 = mt * 128;
    const int n0 = nt * 128;

    float* s_bias = reinterpret_cast<float*>(smem);
    if (tid < 128) s_bias[tid] = bi[n0 + tid];

    const __nv_bfloat16* __restrict__ Ahi = g_TIhi + (size_t)m0 * KIN_;
    const __nv_bfloat16* __restrict__ Alo = g_TIlo + (size_t)m0 * KIN_;
    const __nv_bfloat16* __restrict__ Bhi = g_Wihi + (size_t)n0 * KIN_;
    const __nv_bfloat16* __restrict__ Blo = g_Wilo + (size_t)n0 * KIN_;

    const int lr0 = tid >> 2;
    const int lc0 = (tid & 3);
    const int lr1 = (tid + 256) >> 2;
    const int lc1 = ((tid + 256) & 3);

    auto load_stage = [&](int ch, int stage) {
        const int k0 = ch * BK_;
        const uint32_t base = sb + SMOFF_ + stage * STAGEB_;
        const __nv_bfloat16* srcs[4] = {Ahi, Alo, Bhi, Blo};
#pragma unroll
        for (int tl = 0; tl < 4; tl++) {
            const __nv_bfloat16* s = srcs[tl];
            uint32_t tb = base + tl * TILEB_;
            CP_ASYNC16(tb + lr0 * ROWB_ + lc0 * 16, s + (size_t)lr0 * KIN_ + k0 + lc0 * 8);
            CP_ASYNC16(tb + lr1 * ROWB_ + lc1 * 16, s + (size_t)lr1 * KIN_ + k0 + lc1 * 8);
        }
        CP_COMMIT();
    };

    const int wm = wid >> 2;
    const int wn = wid & 3;
    const int lrow = lid & 15;
    const int lhalf = lid >> 4;

    float acc[4][4][4];
#pragma unroll
    for (int i = 0; i < 4; i++)
#pragma unroll
        for (int j = 0; j < 4; j++)
#pragma unroll
            for (int r = 0; r < 4; r++) acc[i][j][r] = 0.f;

    load_stage(0, 0);

    for (int ch = 0; ch < NCH_; ch++) {
        const int stage = ch & 1;
        if (ch + 1 < NCH_) {
            load_stage(ch + 1, stage ^ 1);
            CP_WAIT(1);
        } else {
            CP_WAIT(0);
        }
        __syncthreads();

        const uint32_t base = sb + SMOFF_ + stage * STAGEB_;
        const uint32_t aHi = base + 0 * TILEB_;
        const uint32_t aLo = base + 1 * TILEB_;
        const uint32_t bHi = base + 2 * TILEB_;
        const uint32_t bLo = base + 3 * TILEB_;

#pragma unroll
        for (int ks = 0; ks < 2; ks++) {
            const uint32_t koff = ks * 32 + lhalf * 16;

            uint32_t a_hi[4][4], a_lo[4][4];
#pragma unroll
            for (int mf = 0; mf < 4; mf++) {
                uint32_t roff = (uint32_t)(wm * 64 + mf * 16 + lrow) * ROWB_ + koff;
                ldsm4(a_hi[mf], aHi + roff);
                ldsm4(a_lo[mf], aLo + roff);
            }
            uint32_t b_hi[2][4], b_lo[2][4];
#pragma unroll
            for (int np = 0; np < 2; np++) {
                uint32_t roff = (uint32_t)(wn * 32 + np * 16 + lrow) * ROWB_ + koff;
                ldsm4(b_hi[np], bHi + roff);
                ldsm4(b_lo[np], bLo + roff);
            }

#pragma unroll
            for (int mf = 0; mf < 4; mf++) {
#pragma unroll
                for (int np = 0; np < 2; np++) {
#pragma unroll
                    for (int q = 0; q < 2; q++) {
                        uint32_t bh[2] = {b_hi[np][q], b_hi[np][q + 2]};
                        uint32_t bl[2] = {b_lo[np][q], b_lo[np][q + 2]};
                        float* d = acc[mf][np * 2 + q];
                        mma16816(d, a_hi[mf], bh);
                        mma16816(d, a_hi[mf], bl);
                        mma16816(d, a_lo[mf], bh);
                    }
                }
            }
        }
        __syncthreads();
    }

    const int trow = lid >> 2;
    const int tcol2 = (lid & 3) * 2;
#pragma unroll
    for (int mf = 0; mf < 4; mf++) {
        int m = m0 + wm * 64 + mf * 16 + trow;
        float* __restrict__ o0 = g_PI + (size_t)m * SIXH_ + n0;
        float* __restrict__ o1 = g_PI + (size_t)(m + 8) * SIXH_ + n0;
#pragma unroll
        for (int nf = 0; nf < 4; nf++) {
            int cn = wn * 32 + nf * 8 + tcol2;
            float b0 = s_bias[cn], b1 = s_bias[cn + 1];
            float2 v0 = make_float2(acc[mf][nf][0] + b0, acc[mf][nf][1] + b1);
            float2 v1 = make_float2(acc[mf][nf][2] + b0, acc[mf][nf][3] + b1);
            *reinterpret_cast<float2*>(o0 + cn) = v0;
            *reinterpret_cast<float2*>(o1 + cn) = v1;
        }
    }
}

// ---------------------------------------------------------------------------
// Generic SGEMM (output GEMM): C = A @ B^T + bias
// ---------------------------------------------------------------------------
__global__ __launch_bounds__(256)
void k_sgemm(int M, int N, int K,
             const float* __restrict__ A,
             const float* __restrict__ B,
             const float* __restrict__ bias,
             float* __restrict__ C) {
    constexpr int BM = 128, BN = 128, BK = 8, TM = 8, TN = 8;
    __shared__ float As[BK][BM];
    __shared__ float Bs[BK][BN];

    const int tid = threadIdx.x;
    const int m0  = blockIdx.y * BM;
    const int n0  = blockIdx.x * BN;
    const int trow = tid / (BN / TN);
    const int tcol = tid % (BN / TN);
    const int a_row = tid >> 1;
    const int a_col = (tid & 1) * 4;

    float acc[TM][TN];
#pragma unroll
    for (int i = 0; i < TM; i++)
#pragma unroll
        for (int j = 0; j < TN; j++) acc[i][j] = 0.f;

    for (int k0 = 0; k0 < K; k0 += BK) {
        {
            int gm = m0 + a_row;
            float4 v = make_float4(0.f, 0.f, 0.f, 0.f);
            if (gm < M) v = *reinterpret_cast<const float4*>(A + (size_t)gm * K + k0 + a_col);
            As[a_col + 0][a_row] = v.x;
            As[a_col + 1][a_row] = v.y;
            As[a_col + 2][a_row] = v.z;
            As[a_col + 3][a_row] = v.w;
        }
        {
            int gn = n0 + a_row;
            float4 v = make_float4(0.f, 0.f, 0.f, 0.f);
            if (gn < N) v = *reinterpret_cast<const float4*>(B + (size_t)gn * K + k0 + a_col);
            Bs[a_col + 0][a_row] = v.x;
            Bs[a_col + 1][a_row] = v.y;
            Bs[a_col + 2][a_row] = v.z;
            Bs[a_col + 3][a_row] = v.w;
        }
        __syncthreads();

#pragma unroll
        for (int kk = 0; kk < BK; kk++) {
            float a[TM], b[TN];
            *reinterpret_cast<float4*>(&a[0]) = *reinterpret_cast<const float4*>(&As[kk][trow * TM + 0]);
            *reinterpret_cast<float4*>(&a[4]) = *reinterpret_cast<const float4*>(&As[kk][trow * TM + 4]);
            *reinterpret_cast<float4*>(&b[0]) = *reinterpret_cast<const float4*>(&Bs[kk][tcol * TN + 0]);
            *reinterpret_cast<float4*>(&b[4]) = *reinterpret_cast<const float4*>(&Bs[kk][tcol * TN + 4]);
#pragma unroll
            for (int i = 0; i < TM; i++)
#pragma unroll
                for (int j = 0; j < TN; j++)
                    acc[i][j] = fmaf(a[i], b[j], acc[i][j]);
        }
        __syncthreads();
    }

#pragma unroll
    for (int i = 0; i < TM; i++) {
        int gm = m0 + trow * TM + i;
        if (gm >= M) continue;
#pragma unroll
        for (int j = 0; j < TN; j++) {
            int gn = n0 + tcol * TN + j;
            if (gn < N) C[(size_t)gm * N + gn] = acc[i][j] + bias[gn];
        }
    }
}

// ---------------------------------------------------------------------------
// Persistent tensor-core recurrence.
//   128 CTAs = 32 n-tiles (16 cols x 5 gates) x 4 b-tiles (64 rows), 256 thr.
//   Ws slice split to bf16 hi/lo at preload, resident in smem (166 KB).
//   Per step: PS = h @ Ws^T via mma.sync 3-term bf16 split; gate epilogue in
//   registers; h(t) split to bf16 hi/lo (double-buffered global) + fp32 g_H.
// ---------------------------------------------------------------------------
__device__ __forceinline__ float sigmoidf_(float x) {
    return 1.f / (1.f + __expf(-x));
}

#define WS_STRIDE 1040                    // bytes per Ws smem row (65 x 16B)
#define WS_TILEB  (80 * WS_STRIDE)        // 83200
#define HS_STRIDE 144                     // bytes per h smem row (9 x 16B)
#define HS_TILEB  (64 * HS_STRIDE)        // 9216
#define SM_H_OFF  (2 * WS_TILEB)          // 166400
#define SMEM_RECUR (2 * WS_TILEB + 4 * HS_TILEB)   // 203264

__global__ __launch_bounds__(256, 1)
void k_recur_mma(const float* __restrict__ Ws,
                 const float* __restrict__ bs,
                 const float* __restrict__ mask)
{
    extern __shared__ char smem[];
    const uint32_t sb = smem_u32(smem);
    const int tid = threadIdx.x;
    const int wid = tid >> 5;
    const int lid = tid & 31;

    const int nt = blockIdx.x & 31;
    const int bt = blockIdx.x >> 5;
    const int n0 = nt * 16;               // column base (within each gate's H)
    const int b0 = bt * 64;               // batch row base

    const int wm = wid >> 1;              // 0..3 (16 rows each)
    const int wn = wid & 1;               // 0..1 (8 cols per gate each)

    __shared__ unsigned s_base;
    if (tid == 0) {
        unsigned v;
        asm volatile("ld.acquire.gpu.global.u32 %0, [%1];" : "=r"(v) : "l"(&g_gen));
        s_base = v;
    }

    // ---- preload + split Ws slice: smem row r = g*16+j  <-  Ws[g*H + n0 + j][:]
    for (int s = tid; s < 80 * 128; s += 256) {
        int r  = s >> 7;                  // 0..79
        int c4 = s & 127;                 // float4 index along K
        int g  = r >> 4, j = r & 15;
        float4 v = *reinterpret_cast<const float4*>(
            Ws + (size_t)(g * H_ + n0 + j) * H_ + c4 * 4);
        uint2 hi, lo;
        split4(v, &hi, &lo);
        uint32_t off = (uint32_t)r * WS_STRIDE + c4 * 8;
        *reinterpret_cast<uint2*>(smem + off) = hi;
        *reinterpret_cast<uint2*>(smem + WS_TILEB + off) = lo;
    }

    // ---- per-thread fragment addressing
    // B (Ws): pair p loads gates (gA[p], gB[p]); lanes 0-7 gA rows, 8-15 gB rows,
    //         16-23 gA +16B, 24-31 gB +16B.
    const int gA[3] = {0, 2, 4};
    const int gB[3] = {1, 3, 4};
    uint32_t brow[3];
#pragma unroll
    for (int p = 0; p < 3; p++) {
        int g = ((lid >> 3) & 1) ? gB[p] : gA[p];
        brow[p] = (uint32_t)((g * 16 + wn * 8 + (lid & 7)) * WS_STRIDE) + ((lid >> 4) * 16);
    }
    // A (h chunk): rows 0-15 at +0, same rows at +16B for lanes 16-31
    const uint32_t arow = (uint32_t)((wm * 16 + (lid & 15)) * HS_STRIDE) + ((lid >> 4) * 16);

    // ---- per-thread epilogue constants
    const int r0 = b0 + wm * 16 + (lid >> 2);       // global batch row (and +8)
    const int c0 = n0 + wn * 8 + (lid & 3) * 2;     // global h column (even)
    float2 bs2[5];
#pragma unroll
    for (int g = 0; g < 5; g++) bs2[g] = *reinterpret_cast<const float2*>(bs + g * H_ + c0);
    float2 mk[2];
    mk[0] = *reinterpret_cast<const float2*>(mask + (size_t)r0 * H_ + c0);
    mk[1] = *reinterpret_cast<const float2*>(mask + (size_t)(r0 + 8) * H_ + c0);
    float2 cst[2] = {{0.f, 0.f}, {0.f, 0.f}};

    __syncthreads();
    const unsigned base = s_base;

    // h-chunk cp.async loader (chunk = 64 rows x 64 bf16 cols, hi+lo)
    auto load_hchunk = [&](int kc, int stage,
                           const __nv_bfloat16* __restrict__ Hhi,
                           const __nv_bfloat16* __restrict__ Hlo) {
        uint32_t db = sb + SM_H_OFF + stage * (2 * HS_TILEB);
#pragma unroll
        for (int s = 0; s < 2; s++) {
            int e = s * 256 + tid;
            int row = e >> 3, c = e & 7;
            size_t goff = (size_t)(b0 + row) * H_ + kc * 64 + c * 8;
            uint32_t soff = (uint32_t)(row * HS_STRIDE + c * 16);
            CP_ASYNC16(db + soff, Hhi + goff);
            CP_ASYNC16(db + HS_TILEB + soff, Hlo + goff);
        }
        CP_COMMIT();
    };

    for (int t = 0; t < T_; t++) {
        float acc[5][4];
#pragma unroll
        for (int g = 0; g < 5; g++)
#pragma unroll
            for (int r = 0; r < 4; r++) acc[g][r] = 0.f;

        // prefetch pi for this thread's 4 outputs (independent of h)
        const float* __restrict__ piB = g_PI + (size_t)t * B_ * SIXH_;
        float2 pf[2][6];
#pragma unroll
        for (int i = 0; i < 2; i++) {
            const float* pir = piB + (size_t)(r0 + i * 8) * SIXH_ + c0;
#pragma unroll
            for (int g = 0; g < 6; g++)
                pf[i][g] = *reinterpret_cast<const float2*>(pir + g * H_);
        }

        if (t > 0) {
            const __nv_bfloat16* __restrict__ Hhi = g_Hhi + ((t - 1) & 1) * (B_ * H_);
            const __nv_bfloat16* __restrict__ Hlo = g_Hlo + ((t - 1) & 1) * (B_ * H_);

            load_hchunk(0, 0, Hhi, Hlo);

            for (int kc = 0; kc < 8; kc++) {
                const int stage = kc & 1;
                if (kc + 1 < 8) {
                    load_hchunk(kc + 1, stage ^ 1, Hhi, Hlo);
                    CP_WAIT(1);
                } else {
                    CP_WAIT(0);
                }
                __syncthreads();

                const uint32_t hb_hi = sb + SM_H_OFF + stage * (2 * HS_TILEB);
                const uint32_t hb_lo = hb_hi + HS_TILEB;
                const uint32_t kcb = (uint32_t)kc * 128;   // k-byte base in Ws rows

#pragma unroll
                for (int ks = 0; ks < 4; ks++) {
                    uint32_t ahi[4], alo[4];
                    ldsm4(ahi, hb_hi + arow + ks * 32);
                    ldsm4(alo, hb_lo + arow + ks * 32);
#pragma unroll
                    for (int p = 0; p < 3; p++) {
                        uint32_t bh[4], bl[4];
                        uint32_t boff = brow[p] + kcb + ks * 32;
                        ldsm4(bh, sb + boff);
                        ldsm4(bl, sb + WS_TILEB + boff);
                        const int qmax = (p == 2) ? 1 : 2;
#pragma unroll
                        for (int q = 0; q < qmax; q++) {
                            const int g = 2 * p + q;
                            uint32_t bhf[2] = {bh[q], bh[q + 2]};
                            uint32_t blf[2] = {bl[q], bl[q + 2]};
                            mma16816(acc[g], ahi, bhf);
                            mma16816(acc[g], ahi, blf);
                            mma16816(acc[g], alo, bhf);
                        }
                    }
                }
                __syncthreads();
            }
        }

        // ---- epilogue: gates + cell + highway + dropout; split h -> bf16
        float* __restrict__ hout = g_H + (size_t)t * B_ * H_;
        __nv_bfloat16* __restrict__ hhi = g_Hhi + (t & 1) * (B_ * H_);
        __nv_bfloat16* __restrict__ hlo = g_Hlo + (t & 1) * (B_ * H_);
#pragma unroll
        for (int i = 0; i < 2; i++) {
            const int r = r0 + i * 8;
            float igx = sigmoidf_(pf[i][0].x + acc[0][2 * i + 0] + bs2[0].x);
            float igy = sigmoidf_(pf[i][0].y + acc[0][2 * i + 1] + bs2[0].y);
            float fgx = sigmoidf_(pf[i][1].x + acc[1][2 * i + 0] + bs2[1].x);
            float fgy = sigmoidf_(pf[i][1].y + acc[1][2 * i + 1] + bs2[1].y);
            float mix = tanhf   (pf[i][2].x + acc[2][2 * i + 0] + bs2[2].x);
            float miy = tanhf   (pf[i][2].y + acc[2][2 * i + 1] + bs2[2].y);
            float ogx = sigmoidf_(pf[i][3].x + acc[3][2 * i + 0] + bs2[3].x);
            float ogy = sigmoidf_(pf[i][3].y + acc[3][2 * i + 1] + bs2[3].y);
            float hgx = sigmoidf_(pf[i][4].x + acc[4][2 * i + 0] + bs2[4].x);
            float hgy = sigmoidf_(pf[i][4].y + acc[4][2 * i + 1] + bs2[4].y);

            float cnx = igx * mix + fgx * cst[i].x;
            float cny = igy * miy + fgy * cst[i].y;
            float ox = ogx * tanhf(cnx);
            float oy = ogy * tanhf(cny);
            ox = hgx * ox + (1.f - hgx) * pf[i][5].x;
            oy = hgy * oy + (1.f - hgy) * pf[i][5].y;
            ox *= mk[i].x;
            oy *= mk[i].y;
            cst[i].x = cnx;
            cst[i].y = cny;

            *reinterpret_cast<float2*>(hout + (size_t)r * H_ + c0) = make_float2(ox, oy);

            __nv_bfloat16 hx = __float2bfloat16_rn(ox);
            __nv_bfloat16 hy = __float2bfloat16_rn(oy);
            __nv_bfloat16 lx = __float2bfloat16_rn(ox - __bfloat162float(hx));
            __nv_bfloat16 ly = __float2bfloat16_rn(oy - __bfloat162float(hy));
            uint32_t ph = (uint32_t)__bfloat16_as_ushort(hy) << 16 | __bfloat16_as_ushort(hx);
            uint32_t pl = (uint32_t)__bfloat16_as_ushort(ly) << 16 | __bfloat16_as_ushort(lx);
            *reinterpret_cast<uint32_t*>(hhi + (size_t)r * H_ + c0) = ph;
            *reinterpret_cast<uint32_t*>(hlo + (size_t)r * H_ + c0) = pl;
        }

        // ---- grid barrier: h(t) visible to all before step t+1
        if (t < T_ - 1) {
            __syncthreads();
            if (tid == 0) {
                __threadfence();
                unsigned prev = atomicAdd(&g_arrive, 1);
                if (prev == NCTA_ - 1) {
                    g_arrive = 0;
                    __threadfence();
                    atomicAdd(&g_gen, 1);
                } else {
                    unsigned target = base + (unsigned)t + 1u;
                    unsigned v;
                    do {
                        asm volatile("ld.acquire.gpu.global.u32 %0, [%1];"
                                     : "=r"(v) : "l"(&g_gen));
                    } while (v - base < target - base);
                }
            }
            __syncthreads();
        }
    }
}

// ---------------------------------------------------------------------------
// kernel_launch
// Input order: x, labels, embed, Wi, bi, Ws, bs, Wo, bo, mask
// ---------------------------------------------------------------------------
extern "C" void kernel_launch(void* const* d_in, const int* in_sizes, int n_in,
                              void* d_out, int out_size) {
    const float* x      = (const float*)d_in[0];
    const int*   labels = (const int*)  d_in[1];
    const float* embed  = (const float*)d_in[2];
    const float* Wi     = (const float*)d_in[3];
    const float* bi     = (const float*)d_in[4];
    const float* Ws     = (const float*)d_in[5];
    const float* bs     = (const float*)d_in[6];
    const float* Wo     = (const float*)d_in[7];
    const float* bo     = (const float*)d_in[8];
    const float* mask   = (const float*)d_in[9];
    float* out = (float*)d_out;

    float* hall;
    cudaGetSymbolAddress((void**)&hall, g_H);

    // 1) split Wi into bf16 hi/lo
    {
        int total = SIXH_ * (KIN_ / 4);
        k_split_w<<<(total + 255) / 256, 256>>>(Wi);
    }
    // 2) concat + split TI into bf16 hi/lo
    {
        int total = M_TOT * (KIN_ / 4);
        k_concat_split<<<(total + 255) / 256, 256>>>(x, labels, embed);
    }
    // 3) PI = TI @ Wi^T + bi via mma.sync bf16 3-term split
    {
        const int smem_bytes = SMOFF_ + 2 * STAGEB_;
        cudaFuncSetAttribute(k_mma1, cudaFuncAttributeMaxDynamicSharedMemorySize, smem_bytes);
        dim3 grid((M_TOT / 128) * (SIXH_ / 128));
        k_mma1<<<grid, 256, smem_bytes>>>(bi);
    }
    // 4) persistent tensor-core recurrence
    {
        cudaFuncSetAttribute(k_recur_mma, cudaFuncAttributeMaxDynamicSharedMemorySize, SMEM_RECUR);
        k_recur_mma<<<NCTA_, 256, SMEM_RECUR>>>(Ws, bs, mask);
    }
    // 5) OUT = H_all @ Wo^T + bo
    {
        dim3 grid((NC_ + 127) / 128, M_TOT / 128);
        k_sgemm<<<grid, 256>>>(M_TOT, NC_, H_, hall, Wo, bo, out);
    }
}